// round 2
// baseline (speedup 1.0000x reference)
#include <cuda_runtime.h>
#include <math.h>

#define NB 256
#define NT 100
#define NI 1024
#define NH 2048
#define NO 1024

// Recurrent state + precomputed constants (static device buffers; no allocs).
__device__ float g_p1[NB * NI];
__device__ float g_p2[NB * NH];
__device__ float g_s1[NB * NI];
__device__ float g_s2[NB * NH];
__device__ float g_acc[NB * NO];
__device__ float g_df1[NI];
__device__ float g_df2[NH];
__device__ float g_tw[NT];

// ---------------------------------------------------------------------------
// Init: zero states, compute delay factors df1/df2.
// ---------------------------------------------------------------------------
__global__ void init_kernel(const float* __restrict__ cd1, const float* __restrict__ v1,
                            const float* __restrict__ cd2, const float* __restrict__ v2) {
    int idx = blockIdx.x * blockDim.x + threadIdx.x;
    if (idx < NB * NH) g_p2[idx] = 0.0f;
    if (idx < NB * NI) g_p1[idx] = 0.0f;
    if (idx < NB * NO) g_acc[idx] = 0.0f;
    if (idx < NI) {
        float vc = fminf(fmaxf(v1[0], 0.0f), 0.999f);
        float gamma = 1.0f / sqrtf(1.0f - vc * vc);
        g_df1[idx] = expf(-(gamma * fabsf(cd1[idx]) * vc));
    }
    if (idx < NH) {
        float vc = fminf(fmaxf(v2[0], 0.0f), 0.999f);
        float gamma = 1.0f / sqrtf(1.0f - vc * vc);
        g_df2[idx] = expf(-(gamma * fabsf(cd2[idx]) * vc));
    }
}

// Time weights: tw[t] = exp(-(gamma1-1)*t) / sum.
__global__ void tw_kernel(const float* __restrict__ v1) {
    __shared__ float sh[128];
    int t = threadIdx.x;
    float vc = fminf(fmaxf(v1[0], 0.0f), 0.999f);
    float gamma = 1.0f / sqrtf(1.0f - vc * vc);
    float e = (t < NT) ? expf(-(gamma - 1.0f) * (float)t) : 0.0f;
    sh[t] = e;
    __syncthreads();
    for (int s = 64; s > 0; s >>= 1) {
        if (t < s) sh[t] += sh[t + s];
        __syncthreads();
    }
    if (t < NT) g_tw[t] = e / sh[0];
}

// LIF1 for t=0 (p1 starts at 0).
__global__ void lif1_first(const float* __restrict__ x) {
    int idx = blockIdx.x * blockDim.x + threadIdx.x;  // over NB*NI
    int b = idx / NI, i = idx % NI;
    float p = x[b * (NT * NI) + i] * g_df1[i];
    bool s = p > 1.0f;
    g_s1[idx] = s ? 1.0f : 0.0f;
    g_p1[idx] = s ? 0.0f : p;
}

// ---------------------------------------------------------------------------
// GEMM1: h = s1 @ W1^T + b1, fused LIF2 epilogue -> s2, p2.
// M=256, N=2048, K=1024. Tiles 64x64, 256 threads, 4x4 per thread.
// Grid (32, 4) = 128 CTAs.
// ---------------------------------------------------------------------------
__global__ void __launch_bounds__(256) gemm1_lif2(const float* __restrict__ W1,
                                                  const float* __restrict__ b1) {
    __shared__ float As[16][68];
    __shared__ float Bs[16][68];
    const int K = NI;
    int tid = threadIdx.x;
    int m0 = blockIdx.y * 64, n0 = blockIdx.x * 64;

    int lrow = tid >> 2;
    int lcol = (tid & 3) << 2;
    const float* Ag = g_s1 + (m0 + lrow) * K + lcol;
    const float* Bg = W1 + (n0 + lrow) * K + lcol;

    int tmy = (tid >> 4) << 2;   // 0..60
    int tnx = (tid & 15) << 2;   // 0..60
    float acc[4][4] = {};

    for (int kb = 0; kb < K; kb += 16) {
        float4 av = *(const float4*)(Ag + kb);
        float4 bv = *(const float4*)(Bg + kb);
        As[lcol + 0][lrow] = av.x; As[lcol + 1][lrow] = av.y;
        As[lcol + 2][lrow] = av.z; As[lcol + 3][lrow] = av.w;
        Bs[lcol + 0][lrow] = bv.x; Bs[lcol + 1][lrow] = bv.y;
        Bs[lcol + 2][lrow] = bv.z; Bs[lcol + 3][lrow] = bv.w;
        __syncthreads();
#pragma unroll
        for (int k = 0; k < 16; k++) {
            float4 a = *(const float4*)&As[k][tmy];
            float4 b = *(const float4*)&Bs[k][tnx];
            float aa[4] = {a.x, a.y, a.z, a.w};
            float bb[4] = {b.x, b.y, b.z, b.w};
#pragma unroll
            for (int i2 = 0; i2 < 4; i2++)
#pragma unroll
                for (int j2 = 0; j2 < 4; j2++)
                    acc[i2][j2] += aa[i2] * bb[j2];
        }
        __syncthreads();
    }

    // Epilogue: h = acc + b1; LIF2 update.
#pragma unroll
    for (int i2 = 0; i2 < 4; i2++) {
        int b_ = m0 + tmy + i2;
#pragma unroll
        for (int j2 = 0; j2 < 4; j2++) {
            int j = n0 + tnx + j2;
            float h = acc[i2][j2] + b1[j];
            int idx = b_ * NH + j;
            float p = g_p2[idx] * 0.9f + h * g_df2[j];
            bool s = p > 0.8f;
            g_s2[idx] = s ? 1.0f : 0.0f;
            g_p2[idx] = s ? 0.0f : p;
        }
    }
}

// ---------------------------------------------------------------------------
// GEMM2: o = s2 @ W2^T; acc += tw[t]*o; fused LIF1 for step t+1.
// M=256, N=1024, K=2048. Tiles 32x64, 256 threads, 2x4 per thread.
// Grid (16, 8) = 128 CTAs. Output tiles exactly cover the [256,1024] LIF1 domain.
// ---------------------------------------------------------------------------
__global__ void __launch_bounds__(256) gemm2_acc_lif1(const float* __restrict__ W2,
                                                      const float* __restrict__ x, int t) {
    __shared__ float As[16][36];
    __shared__ float Bs[16][68];
    const int K = NH;
    int tid = threadIdx.x;
    int m0 = blockIdx.y * 32, n0 = blockIdx.x * 64;

    int lrow = tid >> 2;
    int lcol = (tid & 3) << 2;
    const float* Bg = W2 + (n0 + lrow) * K + lcol;
    const float* Ag = g_s2 + (m0 + lrow) * K + lcol;  // valid for tid < 128

    int tmy = (tid >> 4) << 1;   // 0..30
    int tnx = (tid & 15) << 2;   // 0..60
    float acc[2][4] = {};

    for (int kb = 0; kb < K; kb += 16) {
        float4 bv = *(const float4*)(Bg + kb);
        float4 av;
        if (tid < 128) av = *(const float4*)(Ag + kb);
        Bs[lcol + 0][lrow] = bv.x; Bs[lcol + 1][lrow] = bv.y;
        Bs[lcol + 2][lrow] = bv.z; Bs[lcol + 3][lrow] = bv.w;
        if (tid < 128) {
            As[lcol + 0][lrow] = av.x; As[lcol + 1][lrow] = av.y;
            As[lcol + 2][lrow] = av.z; As[lcol + 3][lrow] = av.w;
        }
        __syncthreads();
#pragma unroll
        for (int k = 0; k < 16; k++) {
            float2 a = *(const float2*)&As[k][tmy];
            float4 b = *(const float4*)&Bs[k][tnx];
            float bb[4] = {b.x, b.y, b.z, b.w};
#pragma unroll
            for (int j2 = 0; j2 < 4; j2++) {
                acc[0][j2] += a.x * bb[j2];
                acc[1][j2] += a.y * bb[j2];
            }
        }
        __syncthreads();
    }

    float tw = g_tw[t];
#pragma unroll
    for (int i2 = 0; i2 < 2; i2++) {
        int b_ = m0 + tmy + i2;
#pragma unroll
        for (int j2 = 0; j2 < 4; j2++) {
            int o = n0 + tnx + j2;
            g_acc[b_ * NO + o] += tw * acc[i2][j2];
            if (t + 1 < NT) {
                int ii = o;  // LIF1 domain index (NO == NI)
                int pidx = b_ * NI + ii;
                float p = g_p1[pidx] * 0.9f +
                          x[b_ * (NT * NI) + (t + 1) * NI + ii] * g_df1[ii];
                bool s = p > 1.0f;
                g_s1[pidx] = s ? 1.0f : 0.0f;
                g_p1[pidx] = s ? 0.0f : p;
            }
        }
    }
}

// Final: out = (acc + b2) * out_scale + out_bias   (sum_t tw = 1 absorbs b2).
__global__ void final_kernel(const float* __restrict__ b2, const float* __restrict__ osc,
                             const float* __restrict__ obi, float* __restrict__ out) {
    int idx = blockIdx.x * blockDim.x + threadIdx.x;  // over NB*NO
    int o = idx & (NO - 1);
    out[idx] = (g_acc[idx] + b2[o]) * osc[o] + obi[o];
}

// ---------------------------------------------------------------------------
extern "C" void kernel_launch(void* const* d_in, const int* in_sizes, int n_in,
                              void* d_out, int out_size) {
    const float* x   = (const float*)d_in[0];
    const float* cd1 = (const float*)d_in[1];
    const float* v1  = (const float*)d_in[2];
    const float* cd2 = (const float*)d_in[3];
    const float* v2  = (const float*)d_in[4];
    const float* W1  = (const float*)d_in[5];
    const float* b1  = (const float*)d_in[6];
    const float* W2  = (const float*)d_in[7];
    const float* b2  = (const float*)d_in[8];
    const float* osc = (const float*)d_in[9];
    const float* obi = (const float*)d_in[10];
    float* out = (float*)d_out;

    init_kernel<<<(NB * NH + 255) / 256, 256>>>(cd1, v1, cd2, v2);
    tw_kernel<<<1, 128>>>(v1);
    lif1_first<<<(NB * NI) / 256, 256>>>(x);

    for (int t = 0; t < NT; t++) {
        gemm1_lif2<<<dim3(NH / 64, NB / 64), 256>>>(W1, b1);
        gemm2_acc_lif1<<<dim3(NO / 64, NB / 32), 256>>>(W2, x, t);
    }

    final_kernel<<<(NB * NO) / 256, 256>>>(b2, osc, obi, out);
}

// round 4
// speedup vs baseline: 2.8228x; 2.8228x over previous
#include <cuda_runtime.h>
#include <cuda_bf16.h>
#include <math.h>
#include <stdint.h>

#define NB 256
#define NT 100
#define NI 1024
#define NH 2048
#define NO 1024

// ---------------------------------------------------------------------------
// Static device state (no allocations allowed).
// ---------------------------------------------------------------------------
__device__ float g_p1[NB * NI];
__device__ float g_p2[NB * NH];
__device__ __nv_bfloat16 g_s1[NB * NI];
__device__ __nv_bfloat16 g_s2[NB * NH];
__device__ float g_acc[NB * NO];
__device__ float g_df1[NI];
__device__ float g_df2[NH];
__device__ float g_tw[NT];
// 3 bf16 limbs per weight: w == l0+l1+l2 to ~2^-24 relative. Spikes are {0,1},
// so every MMA product is exact; accumulation is fp32 inside HMMA.
__device__ __nv_bfloat16 g_W1L[3][NH * NI];
__device__ __nv_bfloat16 g_W2L[3][NO * NH];

// ---------------------------------------------------------------------------
// PTX helpers (arch-agnostic: cp.async / ldmatrix / mma.sync)
// ---------------------------------------------------------------------------
__device__ __forceinline__ uint32_t smem_u32(const void* p) {
    uint32_t a;
    asm("{ .reg .u64 t; cvta.to.shared.u64 t, %1; cvt.u32.u64 %0, t; }" : "=r"(a) : "l"(p));
    return a;
}
__device__ __forceinline__ void cp16(uint32_t s, const void* g) {
    asm volatile("cp.async.cg.shared.global [%0], [%1], 16;" :: "r"(s), "l"(g));
}
#define CP_COMMIT() asm volatile("cp.async.commit_group;" ::: "memory")
#define CP_WAIT(n)  asm volatile("cp.async.wait_group %0;" :: "n"(n) : "memory")

__device__ __forceinline__ void ldsm4(uint32_t* r, uint32_t addr) {
    asm volatile("ldmatrix.sync.aligned.m8n8.x4.shared.b16 {%0,%1,%2,%3}, [%4];"
                 : "=r"(r[0]), "=r"(r[1]), "=r"(r[2]), "=r"(r[3]) : "r"(addr));
}
__device__ __forceinline__ void mma16816(float* c, const uint32_t* a, const uint32_t* b) {
    asm volatile("mma.sync.aligned.m16n8k16.row.col.f32.bf16.bf16.f32 "
                 "{%0,%1,%2,%3}, {%4,%5,%6,%7}, {%8,%9}, {%0,%1,%2,%3};"
                 : "+f"(c[0]), "+f"(c[1]), "+f"(c[2]), "+f"(c[3])
                 : "r"(a[0]), "r"(a[1]), "r"(a[2]), "r"(a[3]), "r"(b[0]), "r"(b[1]));
}

// ---------------------------------------------------------------------------
// Setup kernels
// ---------------------------------------------------------------------------
__global__ void init_kernel(const float* __restrict__ cd1, const float* __restrict__ v1,
                            const float* __restrict__ cd2, const float* __restrict__ v2) {
    int idx = blockIdx.x * blockDim.x + threadIdx.x;
    if (idx < NB * NH) g_p2[idx] = 0.0f;
    if (idx < NB * NI) g_p1[idx] = 0.0f;
    if (idx < NB * NO) g_acc[idx] = 0.0f;
    if (idx < NI) {
        float vc = fminf(fmaxf(v1[0], 0.0f), 0.999f);
        float gamma = 1.0f / sqrtf(1.0f - vc * vc);
        g_df1[idx] = expf(-(gamma * fabsf(cd1[idx]) * vc));
    }
    if (idx < NH) {
        float vc = fminf(fmaxf(v2[0], 0.0f), 0.999f);
        float gamma = 1.0f / sqrtf(1.0f - vc * vc);
        g_df2[idx] = expf(-(gamma * fabsf(cd2[idx]) * vc));
    }
}

__global__ void limbs_kernel(const float* __restrict__ W1, const float* __restrict__ W2) {
    int idx = blockIdx.x * blockDim.x + threadIdx.x;
    if (idx < NH * NI) {
        float w = W1[idx];
        __nv_bfloat16 h0 = __float2bfloat16(w);
        float r = w - __bfloat162float(h0);
        __nv_bfloat16 h1 = __float2bfloat16(r);
        float r2 = r - __bfloat162float(h1);
        g_W1L[0][idx] = h0; g_W1L[1][idx] = h1; g_W1L[2][idx] = __float2bfloat16(r2);
    }
    if (idx < NO * NH) {
        float w = W2[idx];
        __nv_bfloat16 h0 = __float2bfloat16(w);
        float r = w - __bfloat162float(h0);
        __nv_bfloat16 h1 = __float2bfloat16(r);
        float r2 = r - __bfloat162float(h1);
        g_W2L[0][idx] = h0; g_W2L[1][idx] = h1; g_W2L[2][idx] = __float2bfloat16(r2);
    }
}

__global__ void tw_kernel(const float* __restrict__ v1) {
    __shared__ float sh[128];
    int t = threadIdx.x;
    float vc = fminf(fmaxf(v1[0], 0.0f), 0.999f);
    float gamma = 1.0f / sqrtf(1.0f - vc * vc);
    float e = (t < NT) ? expf(-(gamma - 1.0f) * (float)t) : 0.0f;
    sh[t] = e;
    __syncthreads();
    for (int s = 64; s > 0; s >>= 1) {
        if (t < s) sh[t] += sh[t + s];
        __syncthreads();
    }
    if (t < NT) g_tw[t] = e / sh[0];
}

__global__ void lif1_first(const float* __restrict__ x) {
    int idx = blockIdx.x * blockDim.x + threadIdx.x;  // over NB*NI
    int b = idx / NI, i = idx % NI;
    float p = x[b * (NT * NI) + i] * g_df1[i];
    bool s = p > 1.0f;
    g_s1[idx] = __float2bfloat16(s ? 1.0f : 0.0f);
    g_p1[idx] = s ? 0.0f : p;
}

// ---------------------------------------------------------------------------
// HMMA GEMM + fused LIF epilogue.
// WHICH==1: h = s1 @ W1^T (+b1) -> LIF2 -> s2,p2.  M=256,N=2048,K=1024.
//           CTA tile 64x64, grid (32,4)=128. Warps 2x2, warp tile 32x32.
// WHICH==2: o = s2 @ W2^T; acc += tw[t]*o; LIF1(t+1). M=256,N=1024,K=2048.
//           CTA tile 32x64, grid (16,8)=128. Warps 1x4, warp tile 32x16.
// K streamed in 32-wide chunks (double-buffered cp.async); A tile loaded once
// per chunk, reused by all 3 weight limbs (limbs inner).
// ---------------------------------------------------------------------------
template <int WHICH>
__global__ void __launch_bounds__(128) snn_mma(const float* __restrict__ b1,
                                               const float* __restrict__ x, int t) {
    constexpr int K    = (WHICH == 1) ? NI : NH;
    constexpr int NOUT = (WHICH == 1) ? NH : NO;
    constexpr int BM   = (WHICH == 1) ? 64 : 32;
    constexpr int BN   = 64;
    constexpr int NWM  = (WHICH == 1) ? 2 : 1;   // warps along M
    constexpr int WNSZ = BN / (4 / NWM);          // warp N extent (32 or 16)
    constexpr int NT4  = WNSZ / 8;                // n8 tiles per warp (4 or 2)
    constexpr int NTP  = WNSZ / 16;               // n16 ldmatrix pairs (2 or 1)
    constexpr int NCH  = K / 32;
    constexpr size_t LSTR = (size_t)NH * NI;      // limb stride (== NO*NH)

    const __nv_bfloat16* A  = (WHICH == 1) ? g_s1 : g_s2;
    const __nv_bfloat16* BL = (WHICH == 1) ? &g_W1L[0][0] : &g_W2L[0][0];

    __shared__ __nv_bfloat16 As[2][BM][40];
    __shared__ __nv_bfloat16 Bs[2][3][BN][40];

    int tid = threadIdx.x, lane = tid & 31, w = tid >> 5;
    int m0 = blockIdx.y * BM, n0 = blockIdx.x * BN;
    int wm = (w % NWM) * 32, wn = (w / NWM) * WNSZ;

    // ---- chunk loader ----
    auto load_chunk = [&](int kc, int buf) {
#pragma unroll
        for (int p = 0; p < BM / 32; p++) {
            int idx = p * 128 + tid;
            int row = idx >> 2, cg = idx & 3;
            cp16(smem_u32(&As[buf][row][cg * 8]),
                 A + (size_t)(m0 + row) * K + kc * 32 + cg * 8);
        }
#pragma unroll
        for (int p = 0; p < 6; p++) {
            int idx = p * 128 + tid;
            int l = idx >> 8, rem = idx & 255, row = rem >> 2, cg = rem & 3;
            cp16(smem_u32(&Bs[buf][l][row][cg * 8]),
                 BL + (size_t)l * LSTR + (size_t)(n0 + row) * K + kc * 32 + cg * 8);
        }
        CP_COMMIT();
    };

    float acc[2][NT4][4] = {};

    load_chunk(0, 0);
    for (int c = 0; c < NCH; c++) {
        int cur = c & 1;
        if (c + 1 < NCH) { load_chunk(c + 1, cur ^ 1); CP_WAIT(1); }
        else             { CP_WAIT(0); }
        __syncthreads();

#pragma unroll
        for (int ks = 0; ks < 2; ks++) {
            uint32_t a[2][4];
#pragma unroll
            for (int mt = 0; mt < 2; mt++) {
                int j = lane >> 3, r = lane & 7;
                ldsm4(a[mt], smem_u32(&As[cur][wm + mt * 16 + (j & 1) * 8 + r]
                                        [ks * 16 + (j >> 1) * 8]));
            }
#pragma unroll
            for (int l = 0; l < 3; l++) {
                uint32_t b[NTP][4];
#pragma unroll
                for (int np = 0; np < NTP; np++) {
                    int j = lane >> 3, r = lane & 7;
                    ldsm4(b[np], smem_u32(&Bs[cur][l][wn + np * 16 + (j >> 1) * 8 + r]
                                            [ks * 16 + (j & 1) * 8]));
                }
#pragma unroll
                for (int mt = 0; mt < 2; mt++)
#pragma unroll
                    for (int nt = 0; nt < NT4; nt++)
                        mma16816(acc[mt][nt], a[mt], &b[nt >> 1][(nt & 1) * 2]);
            }
        }
        __syncthreads();
    }

    // ---- fused epilogue (each thread owns float2 groups) ----
    int qr = lane >> 2, qc = (lane & 3) * 2;
#pragma unroll
    for (int mt = 0; mt < 2; mt++) {
#pragma unroll
        for (int h = 0; h < 2; h++) {
            int m = m0 + wm + mt * 16 + qr + h * 8;
#pragma unroll
            for (int nt = 0; nt < NT4; nt++) {
                int n = n0 + wn + nt * 8 + qc;
                float v0 = acc[mt][nt][h * 2 + 0];
                float v1 = acc[mt][nt][h * 2 + 1];
                size_t idx = (size_t)m * NOUT + n;
                if (WHICH == 1) {
                    float2 bv = *(const float2*)(b1 + n);
                    float2 fv = *(const float2*)(g_df2 + n);
                    float2 pv = *(float2*)(g_p2 + idx);
                    float p0 = pv.x * 0.9f + (v0 + bv.x) * fv.x;
                    float p1 = pv.y * 0.9f + (v1 + bv.y) * fv.y;
                    bool s0 = p0 > 0.8f, s1 = p1 > 0.8f;
                    *(float2*)(g_p2 + idx) = make_float2(s0 ? 0.f : p0, s1 ? 0.f : p1);
                    *(uint32_t*)(g_s2 + idx) =
                        (s0 ? 0x3F80u : 0u) | ((s1 ? 0x3F80u : 0u) << 16);
                } else {
                    float tw = g_tw[t];
                    float2 av = *(float2*)(g_acc + idx);
                    av.x += tw * v0;
                    av.y += tw * v1;
                    *(float2*)(g_acc + idx) = av;
                    if (t + 1 < NT) {
                        float2 xv = *(const float2*)(x + (size_t)m * (NT * NI) +
                                                     (size_t)(t + 1) * NI + n);
                        float2 fv = *(const float2*)(g_df1 + n);
                        float2 pv = *(float2*)(g_p1 + idx);
                        float p0 = pv.x * 0.9f + xv.x * fv.x;
                        float p1 = pv.y * 0.9f + xv.y * fv.y;
                        bool s0 = p0 > 1.0f, s1 = p1 > 1.0f;
                        *(float2*)(g_p1 + idx) = make_float2(s0 ? 0.f : p0, s1 ? 0.f : p1);
                        *(uint32_t*)(g_s1 + idx) =
                            (s0 ? 0x3F80u : 0u) | ((s1 ? 0x3F80u : 0u) << 16);
                    }
                }
            }
        }
    }
}

// Final: out = (acc + b2) * out_scale + out_bias  (sum_t tw == 1 absorbs b2).
__global__ void final_kernel(const float* __restrict__ b2, const float* __restrict__ osc,
                             const float* __restrict__ obi, float* __restrict__ out) {
    int idx = blockIdx.x * blockDim.x + threadIdx.x;
    int o = idx & (NO - 1);
    out[idx] = (g_acc[idx] + b2[o]) * osc[o] + obi[o];
}

// ---------------------------------------------------------------------------
extern "C" void kernel_launch(void* const* d_in, const int* in_sizes, int n_in,
                              void* d_out, int out_size) {
    const float* x   = (const float*)d_in[0];
    const float* cd1 = (const float*)d_in[1];
    const float* v1  = (const float*)d_in[2];
    const float* cd2 = (const float*)d_in[3];
    const float* v2  = (const float*)d_in[4];
    const float* W1  = (const float*)d_in[5];
    const float* b1  = (const float*)d_in[6];
    const float* W2  = (const float*)d_in[7];
    const float* b2  = (const float*)d_in[8];
    const float* osc = (const float*)d_in[9];
    const float* obi = (const float*)d_in[10];
    float* out = (float*)d_out;

    init_kernel<<<(NB * NH + 255) / 256, 256>>>(cd1, v1, cd2, v2);
    limbs_kernel<<<(NH * NI + 255) / 256, 256>>>(W1, W2);
    tw_kernel<<<1, 128>>>(v1);
    lif1_first<<<(NB * NI) / 256, 256>>>(x);

    for (int t = 0; t < NT; t++) {
        snn_mma<1><<<dim3(NH / 64, NB / 64), 128>>>(b1, x, t);
        snn_mma<2><<<dim3(NO / 64, NB / 32), 128>>>(b1, x, t);
    }

    final_kernel<<<(NB * NO) / 256, 256>>>(b2, osc, obi, out);
}